// round 2
// baseline (speedup 1.0000x reference)
#include <cuda_runtime.h>
#include <cuda_bf16.h>

#define IMG_H 512
#define IMG_W 512
#define IMG_HW (IMG_H * IMG_W)
#define OUT_H 510
#define OUT_W 510
#define NWIN (OUT_H * OUT_W)      // 260100 windows
#define BLOCK 256
#define NWARP (BLOCK / 32)
#define NBLK ((NWIN + BLOCK - 1) / BLOCK)  // 1017

// Scratch for deterministic fused reduction (no device allocation allowed).
__device__ double g_partials[NBLK];
__device__ unsigned int g_ticket = 0;

__global__ void __launch_bounds__(BLOCK) ml_fused_kernel(
    const float* __restrict__ tgt, const float* __restrict__ sty,
    float* __restrict__ out)
{
    const int n = blockIdx.x * BLOCK + threadIdx.x;

    float contrib = 0.0f;
    if (n < NWIN) {
        const int r = n / OUT_W;
        const int c = n - r * OUT_W;
        const int base = r * IMG_W + c;

        // Load 3x3 window for 3 channels of target and style.
        float I[3][9];
        float V[3][9];
        #pragma unroll
        for (int ch = 0; ch < 3; ch++) {
            #pragma unroll
            for (int dr = 0; dr < 3; dr++) {
                #pragma unroll
                for (int dc = 0; dc < 3; dc++) {
                    const int off = ch * IMG_HW + base + dr * IMG_W + dc;
                    I[ch][dr * 3 + dc] = __ldg(tgt + off);
                    V[ch][dr * 3 + dc] = __ldg(sty + off);
                }
            }
        }

        const float inv9 = 1.0f / 9.0f;
        const float eps9 = 1e-7f / 9.0f;

        // Channel sums and Gram matrix (symmetric, 6 unique entries).
        float s0 = 0.f, s1 = 0.f, s2 = 0.f;
        float g00 = 0.f, g01 = 0.f, g02 = 0.f, g11 = 0.f, g12 = 0.f, g22 = 0.f;
        #pragma unroll
        for (int k = 0; k < 9; k++) {
            const float a = I[0][k], b = I[1][k], d = I[2][k];
            s0 += a; s1 += b; s2 += d;
            g00 += a * a; g01 += a * b; g02 += a * d;
            g11 += b * b; g12 += b * d; g22 += d * d;
        }
        const float mu0 = s0 * inv9, mu1 = s1 * inv9, mu2 = s2 * inv9;

        // Covariance + eps/9 * I  (win_var in the reference)
        g00 = g00 * inv9 - mu0 * mu0 + eps9;
        g01 = g01 * inv9 - mu0 * mu1;
        g02 = g02 * inv9 - mu0 * mu2;
        g11 = g11 * inv9 - mu1 * mu1 + eps9;
        g12 = g12 * inv9 - mu1 * mu2;
        g22 = g22 * inv9 - mu2 * mu2 + eps9;

        // Adjugate (symmetric) and determinant of the 3x3 covariance.
        const float adj00 = g11 * g22 - g12 * g12;
        const float adj01 = g02 * g12 - g01 * g22;
        const float adj02 = g01 * g12 - g02 * g11;
        const float adj11 = g00 * g22 - g02 * g02;
        const float adj12 = g01 * g02 - g00 * g12;
        const float adj22 = g00 * g11 - g01 * g01;
        const float det = g00 * adj00 + g01 * adj01 + g02 * adj02;
        const float invdet = 1.0f / det;

        // Per-channel quadratic form:
        // score_c = |v|^2 - (s^2 + y^T adj y / det) / 9,  y = I^T v - mu * s
        #pragma unroll
        for (int ch = 0; ch < 3; ch++) {
            float s = 0.f, q = 0.f, y0 = 0.f, y1 = 0.f, y2 = 0.f;
            #pragma unroll
            for (int k = 0; k < 9; k++) {
                const float v = V[ch][k];
                s += v;
                q += v * v;
                y0 += I[0][k] * v;
                y1 += I[1][k] * v;
                y2 += I[2][k] * v;
            }
            y0 -= mu0 * s;
            y1 -= mu1 * s;
            y2 -= mu2 * s;
            const float quad = adj00 * y0 * y0 + adj11 * y1 * y1 + adj22 * y2 * y2
                             + 2.0f * (adj01 * y0 * y1 + adj02 * y0 * y2 + adj12 * y1 * y2);
            contrib += q - (s * s + quad * invdet) * inv9;
        }
    }

    // ---- Block reduction: warp shuffles (deterministic fixed tree) ----
    double acc = (double)contrib;
    #pragma unroll
    for (int off = 16; off > 0; off >>= 1)
        acc += __shfl_down_sync(0xFFFFFFFFu, acc, off);

    __shared__ double warp_sums[NWARP];
    const int lane = threadIdx.x & 31;
    const int wid = threadIdx.x >> 5;
    if (lane == 0) warp_sums[wid] = acc;
    __syncthreads();

    __shared__ bool is_last;
    if (threadIdx.x == 0) {
        double bsum = 0.0;
        #pragma unroll
        for (int i = 0; i < NWARP; i++) bsum += warp_sums[i];
        g_partials[blockIdx.x] = bsum;
        __threadfence();
        unsigned int t = atomicAdd(&g_ticket, 1u);
        is_last = (t == (unsigned)(NBLK - 1));
    }
    __syncthreads();

    // ---- Last block performs the final deterministic reduction ----
    if (is_last) {
        __threadfence();
        double a = 0.0;
        for (int i = threadIdx.x; i < NBLK; i += BLOCK) a += g_partials[i];
        #pragma unroll
        for (int off = 16; off > 0; off >>= 1)
            a += __shfl_down_sync(0xFFFFFFFFu, a, off);
        if (lane == 0) warp_sums[wid] = a;
        __syncthreads();
        if (threadIdx.x == 0) {
            double tot = 0.0;
            #pragma unroll
            for (int i = 0; i < NWARP; i++) tot += warp_sums[i];
            out[0] = (float)tot;
            g_ticket = 0;   // reset for next graph replay
        }
    }
}

extern "C" void kernel_launch(void* const* d_in, const int* in_sizes, int n_in,
                              void* d_out, int out_size)
{
    const float* tgt = (const float*)d_in[0];   // target  (3, 512, 512) fp32
    const float* sty = (const float*)d_in[1];   // style   (3, 512, 512) fp32
    float* out = (float*)d_out;

    ml_fused_kernel<<<NBLK, BLOCK>>>(tgt, sty, out);
}

// round 3
// speedup vs baseline: 1.1426x; 1.1426x over previous
#include <cuda_runtime.h>
#include <cuda_bf16.h>

#define IMG_H 512
#define IMG_W 512
#define IMG_HW (IMG_H * IMG_W)
#define OUT_H 510
#define OUT_W 510
#define NWIN (OUT_H * OUT_W)      // 260100 windows
#define BLOCK 256
#define NWARP (BLOCK / 32)
#define NBLK ((NWIN + BLOCK - 1) / BLOCK)  // 1017

// Scratch for deterministic fused reduction (no device allocation allowed).
__device__ double g_partials[NBLK];
__device__ unsigned int g_ticket = 0;

__global__ void __launch_bounds__(BLOCK, 4) ml_fused_kernel(
    const float* __restrict__ tgt, const float* __restrict__ sty,
    float* __restrict__ out)
{
    const int n = blockIdx.x * BLOCK + threadIdx.x;

    float contrib = 0.0f;
    if (n < NWIN) {
        const int r = n / OUT_W;
        const int c = n - r * OUT_W;
        const int base = r * IMG_W + c;

        const float inv9 = 1.0f / 9.0f;
        const float eps9 = 1e-7f / 9.0f;

        // ---- Load target window (27 values) and build I-stats ----
        float I[3][9];
        #pragma unroll
        for (int ch = 0; ch < 3; ch++) {
            #pragma unroll
            for (int dr = 0; dr < 3; dr++) {
                #pragma unroll
                for (int dc = 0; dc < 3; dc++) {
                    I[ch][dr * 3 + dc] = __ldg(tgt + ch * IMG_HW + base + dr * IMG_W + dc);
                }
            }
        }

        float s0 = 0.f, s1 = 0.f, s2 = 0.f;
        float g00 = 0.f, g01 = 0.f, g02 = 0.f, g11 = 0.f, g12 = 0.f, g22 = 0.f;
        #pragma unroll
        for (int k = 0; k < 9; k++) {
            const float a = I[0][k], b = I[1][k], d = I[2][k];
            s0 += a; s1 += b; s2 += d;
            g00 += a * a; g01 += a * b; g02 += a * d;
            g11 += b * b; g12 += b * d; g22 += d * d;
        }
        const float mu0 = s0 * inv9, mu1 = s1 * inv9, mu2 = s2 * inv9;

        // Covariance + eps/9 * I  (win_var in the reference)
        g00 = g00 * inv9 - mu0 * mu0 + eps9;
        g01 = g01 * inv9 - mu0 * mu1;
        g02 = g02 * inv9 - mu0 * mu2;
        g11 = g11 * inv9 - mu1 * mu1 + eps9;
        g12 = g12 * inv9 - mu1 * mu2;
        g22 = g22 * inv9 - mu2 * mu2 + eps9;

        // Adjugate (symmetric) and determinant of the 3x3 covariance.
        const float adj00 = g11 * g22 - g12 * g12;
        const float adj01 = g02 * g12 - g01 * g22;
        const float adj02 = g01 * g12 - g02 * g11;
        const float adj11 = g00 * g22 - g02 * g02;
        const float adj12 = g01 * g02 - g00 * g12;
        const float adj22 = g00 * g11 - g01 * g01;
        const float det = g00 * adj00 + g01 * adj01 + g02 * adj02;
        const float invdet = 1.0f / det;

        // ---- Per style channel: load 9 values, compute quadratic form ----
        // score_c = |v|^2 - (s^2 + y^T adj y / det) / 9,  y = I^T v - mu * s
        #pragma unroll
        for (int ch = 0; ch < 3; ch++) {
            float V[9];
            #pragma unroll
            for (int dr = 0; dr < 3; dr++) {
                #pragma unroll
                for (int dc = 0; dc < 3; dc++) {
                    V[dr * 3 + dc] = __ldg(sty + ch * IMG_HW + base + dr * IMG_W + dc);
                }
            }
            float s = 0.f, q = 0.f, y0 = 0.f, y1 = 0.f, y2 = 0.f;
            #pragma unroll
            for (int k = 0; k < 9; k++) {
                const float v = V[k];
                s += v;
                q += v * v;
                y0 += I[0][k] * v;
                y1 += I[1][k] * v;
                y2 += I[2][k] * v;
            }
            y0 -= mu0 * s;
            y1 -= mu1 * s;
            y2 -= mu2 * s;
            const float quad = adj00 * y0 * y0 + adj11 * y1 * y1 + adj22 * y2 * y2
                             + 2.0f * (adj01 * y0 * y1 + adj02 * y0 * y2 + adj12 * y1 * y2);
            contrib += q - (s * s + quad * invdet) * inv9;
        }
    }

    // ---- Block reduction: warp shuffles (deterministic fixed tree) ----
    double acc = (double)contrib;
    #pragma unroll
    for (int off = 16; off > 0; off >>= 1)
        acc += __shfl_down_sync(0xFFFFFFFFu, acc, off);

    __shared__ double warp_sums[NWARP];
    const int lane = threadIdx.x & 31;
    const int wid = threadIdx.x >> 5;
    if (lane == 0) warp_sums[wid] = acc;
    __syncthreads();

    __shared__ bool is_last;
    if (threadIdx.x == 0) {
        double bsum = 0.0;
        #pragma unroll
        for (int i = 0; i < NWARP; i++) bsum += warp_sums[i];
        // Plain STG (write-through to L2), ordered by the release atomic below.
        g_partials[blockIdx.x] = bsum;
        unsigned int t;
        asm volatile("atom.release.gpu.global.add.u32 %0, [%1], %2;"
                     : "=r"(t) : "l"(&g_ticket), "r"(1u) : "memory");
        is_last = (t == (unsigned)(NBLK - 1));
    }
    __syncthreads();

    // ---- Last block performs the final deterministic reduction ----
    if (is_last) {
        double a = 0.0;
        for (int i = threadIdx.x; i < NBLK; i += BLOCK) {
            double v;
            asm volatile("ld.acquire.gpu.global.f64 %0, [%1];"
                         : "=d"(v) : "l"(&g_partials[i]) : "memory");
            a += v;
        }
        #pragma unroll
        for (int off = 16; off > 0; off >>= 1)
            a += __shfl_down_sync(0xFFFFFFFFu, a, off);
        if (lane == 0) warp_sums[wid] = a;
        __syncthreads();
        if (threadIdx.x == 0) {
            double tot = 0.0;
            #pragma unroll
            for (int i = 0; i < NWARP; i++) tot += warp_sums[i];
            out[0] = (float)tot;
            g_ticket = 0;   // reset for next graph replay
        }
    }
}

extern "C" void kernel_launch(void* const* d_in, const int* in_sizes, int n_in,
                              void* d_out, int out_size)
{
    const float* tgt = (const float*)d_in[0];   // target  (3, 512, 512) fp32
    const float* sty = (const float*)d_in[1];   // style   (3, 512, 512) fp32
    float* out = (float*)d_out;

    ml_fused_kernel<<<NBLK, BLOCK>>>(tgt, sty, out);
}